// round 7
// baseline (speedup 1.0000x reference)
#include <cuda_runtime.h>
#include <cuda_fp16.h>
#include <cstdint>

#define IN_F  4096
#define OUT_F 4096
#define MTOT  2048
#define NGRP  32          // IN_F / 128

// fp16 scratch (device globals: no allocation in kernel_launch)
__device__ __half g_wh[(size_t)OUT_F * IN_F];   // w_q * s_w, [o, k] K-major
__device__ __half g_xh[(size_t)MTOT  * IN_F];   // permuted x, [m, k] K-major

// ------------------------------------------------------------------ helpers
__device__ __forceinline__ uint32_t smem_u32(const void* p) {
    uint32_t a;
    asm("{ .reg .u64 t; cvta.to.shared.u64 t, %1; cvt.u32.u64 %0, t; }" : "=r"(a) : "l"(p));
    return a;
}

// 128B-row swizzle: XOR 16B-chunk index with row (bits 7..9 -> bits 4..6)
__device__ __forceinline__ uint32_t sw128(uint32_t off) { return off ^ ((off >> 3) & 0x70); }

__device__ __forceinline__ void cpa16(uint32_t dst, const void* src) {
    asm volatile("cp.async.cg.shared.global [%0], [%1], 16;" :: "r"(dst), "l"(src));
}

#define LDSM4(r0, r1, r2, r3, addr) \
    asm volatile("ldmatrix.sync.aligned.m8n8.x4.shared.b16 {%0,%1,%2,%3}, [%4];" \
        : "=r"(r0), "=r"(r1), "=r"(r2), "=r"(r3) : "r"(addr))

#define MMA16816(d0, d1, d2, d3, a0, a1, a2, a3, b0, b1) \
    asm volatile("mma.sync.aligned.m16n8k16.row.col.f32.f16.f16.f32 " \
        "{%0,%1,%2,%3},{%4,%5,%6,%7},{%8,%9},{%0,%1,%2,%3};" \
        : "+f"(d0), "+f"(d1), "+f"(d2), "+f"(d3) \
        : "r"(a0), "r"(a1), "r"(a2), "r"(a3), "r"(b0), "r"(b1))

// ---------------------------------------------------------- fused prep
// blocks [0, 4096):       w-row o = blockIdx.x; 256 thr x 16 elems, scales staged in smem
// blocks [4096, 6144):    x-row m = blockIdx.x - 4096; permute + fp32->fp16
__global__ void __launch_bounds__(256) prep_kernel(const int* __restrict__ wq,
                                                   const float* __restrict__ sw,
                                                   const float* __restrict__ x,
                                                   const int* __restrict__ perm32) {
    __shared__ float row[IN_F];          // x-branch row cache; w-branch uses first 32 floats
    __shared__ int is64s;
    const int tid = threadIdx.x;

    if (blockIdx.x < 4096) {
        const int o = blockIdx.x;
        if (tid < NGRP) row[tid] = sw[tid * OUT_F + o];
        __syncthreads();
        const float s = row[tid >> 3];                  // group = (tid*16)/128 = tid>>3
        const int k0 = tid * 16;
        const int4* p = reinterpret_cast<const int4*>(wq + (size_t)o * IN_F + k0);
        int4 w0 = p[0], w1 = p[1], w2 = p[2], w3 = p[3];
        uint4 v0, v1;
        {
            __half2 h0 = __floats2half2_rn(w0.x * s, w0.y * s);
            __half2 h1 = __floats2half2_rn(w0.z * s, w0.w * s);
            __half2 h2 = __floats2half2_rn(w1.x * s, w1.y * s);
            __half2 h3 = __floats2half2_rn(w1.z * s, w1.w * s);
            v0.x = *reinterpret_cast<uint32_t*>(&h0);
            v0.y = *reinterpret_cast<uint32_t*>(&h1);
            v0.z = *reinterpret_cast<uint32_t*>(&h2);
            v0.w = *reinterpret_cast<uint32_t*>(&h3);
        }
        {
            __half2 h0 = __floats2half2_rn(w2.x * s, w2.y * s);
            __half2 h1 = __floats2half2_rn(w2.z * s, w2.w * s);
            __half2 h2 = __floats2half2_rn(w3.x * s, w3.y * s);
            __half2 h3 = __floats2half2_rn(w3.z * s, w3.w * s);
            v1.x = *reinterpret_cast<uint32_t*>(&h0);
            v1.y = *reinterpret_cast<uint32_t*>(&h1);
            v1.z = *reinterpret_cast<uint32_t*>(&h2);
            v1.w = *reinterpret_cast<uint32_t*>(&h3);
        }
        uint4* dst = reinterpret_cast<uint4*>(g_wh + (size_t)o * IN_F + k0);
        dst[0] = v0;
        dst[1] = v1;
        return;
    }

    const int m = blockIdx.x - 4096;
    const float4* src = reinterpret_cast<const float4*>(x + (size_t)m * IN_F);
#pragma unroll
    for (int i = 0; i < 4; ++i)
        reinterpret_cast<float4*>(row)[tid + i * 256] = src[tid + i * 256];
    if (tid == 0) {
        // jnp int64 vs int32 detection: int64 LE => odd 32-bit words all zero.
        int acc = 0;
#pragma unroll
        for (int t = 1; t < 32; t += 2) acc |= perm32[t];
        is64s = (acc == 0) ? 1 : 0;
    }
    __syncthreads();
    const int sh = is64s;
    const int j0 = tid * 16;
    __half* dst = g_xh + (size_t)m * IN_F + j0;
#pragma unroll
    for (int h = 0; h < 2; ++h) {
        int jb = j0 + h * 8;
        float v[8];
#pragma unroll
        for (int i = 0; i < 8; ++i) v[i] = row[perm32[(jb + i) << sh]];
        __half2 p0 = __floats2half2_rn(v[0], v[1]);
        __half2 p1 = __floats2half2_rn(v[2], v[3]);
        __half2 p2 = __floats2half2_rn(v[4], v[5]);
        __half2 p3 = __floats2half2_rn(v[6], v[7]);
        uint4 u;
        u.x = *reinterpret_cast<uint32_t*>(&p0);
        u.y = *reinterpret_cast<uint32_t*>(&p1);
        u.z = *reinterpret_cast<uint32_t*>(&p2);
        u.w = *reinterpret_cast<uint32_t*>(&p3);
        *reinterpret_cast<uint4*>(dst + h * 8) = u;
    }
}

// ---------------------------------------------------------- GEMM: mma.sync (HMMA) f16->f32
// CTA tile 256(M) x 128(N) x 128(K). 512 threads = 16 warps in 4(M) x 4(N),
// warp tile 64x32 -> 4 warps per SMSP (vs 2 before) to fill tensor-issue gaps.
// 2-stage cp.async pipeline, stage = 96KB (A 64KB + B 32KB), 192KB smem, 1 CTA/SM.
static constexpr int BK          = 128;
static constexpr int NITER       = IN_F / BK;         // 32
static constexpr uint32_t A_BYTES     = 65536;        // 2 x 32KB (kh halves)
static constexpr uint32_t STAGE_BYTES = 98304;
static constexpr uint32_t GEMM_SMEM   = 2 * STAGE_BYTES;  // 196608

__device__ __forceinline__ void load_stage(uint32_t sb, int m0, int n0, int j, int tid) {
    const int k0 = j * BK;
#pragma unroll
    for (int kh = 0; kh < 2; ++kh) {
#pragma unroll
        for (int c = 0; c < 4; ++c) {             // A half: 256 rows x 8 chunks of 16B
            int idx = tid + c * 512;
            int row = idx >> 3, ch = idx & 7;
            cpa16(sb + (uint32_t)kh * 32768u + sw128((uint32_t)row * 128u + (uint32_t)ch * 16u),
                  g_xh + (size_t)(m0 + row) * IN_F + k0 + kh * 64 + ch * 8);
        }
#pragma unroll
        for (int c = 0; c < 2; ++c) {             // B half: 128 rows x 8 chunks
            int idx = tid + c * 512;
            int row = idx >> 3, ch = idx & 7;
            cpa16(sb + A_BYTES + (uint32_t)kh * 16384u + sw128((uint32_t)row * 128u + (uint32_t)ch * 16u),
                  g_wh + (size_t)(n0 + row) * IN_F + k0 + kh * 64 + ch * 8);
        }
    }
}

// Fragments for k-step s (s in 0..7: kh = s>>2, ks = s&3); warp tile 64(M) x 32(N)
__device__ __forceinline__ void frag_load(uint32_t sA, uint32_t sB, int s,
                                          int arow_l, int a_c, int brow_l, int b_c,
                                          int wm, int wn, uint32_t a[4][4], uint32_t b[2][4]) {
    const uint32_t aBase = sA + (uint32_t)(s >> 2) * 32768u;
    const uint32_t bBase = sB + (uint32_t)(s >> 2) * 16384u;
    const int ks = s & 3;
#pragma unroll
    for (int mi = 0; mi < 4; ++mi) {
        uint32_t off = (uint32_t)((wm * 64 + mi * 16 + arow_l) * 128 + (ks * 2 + a_c) * 16);
        LDSM4(a[mi][0], a[mi][1], a[mi][2], a[mi][3], aBase + sw128(off));
    }
#pragma unroll
    for (int nb = 0; nb < 2; ++nb) {
        uint32_t off = (uint32_t)((wn * 32 + nb * 16 + brow_l) * 128 + (ks * 2 + b_c) * 16);
        LDSM4(b[nb][0], b[nb][1], b[nb][2], b[nb][3], bBase + sw128(off));
    }
}

__device__ __forceinline__ void frag_mma(const uint32_t a[4][4], const uint32_t b[2][4],
                                         float acc[4][4][4]) {
#pragma unroll
    for (int mi = 0; mi < 4; ++mi)
#pragma unroll
        for (int ni = 0; ni < 4; ++ni) {
            uint32_t b0 = b[ni >> 1][(ni & 1) * 2];
            uint32_t b1 = b[ni >> 1][(ni & 1) * 2 + 1];
            MMA16816(acc[mi][ni][0], acc[mi][ni][1], acc[mi][ni][2], acc[mi][ni][3],
                     a[mi][0], a[mi][1], a[mi][2], a[mi][3], b0, b1);
        }
}

__global__ void __launch_bounds__(512, 1) gemm_kernel(const float* __restrict__ bias,
                                                      float* __restrict__ out) {
    extern __shared__ char smem[];
    const uint32_t sbase = smem_u32(smem);
    const int tid  = threadIdx.x;
    const int lane = tid & 31, wid = tid >> 5;
    const int wm = wid & 3, wn = wid >> 2;        // 4 x 4 warp grid
    const int n0 = blockIdx.x * 128, m0 = blockIdx.y * 256;

    // ldmatrix per-lane addressing constants
    const int arow_l = (lane & 7) + ((lane >> 3) & 1) * 8;
    const int a_c    = lane >> 4;
    const int brow_l = (lane & 7) + ((lane >> 4) & 1) * 8;
    const int b_c    = (lane >> 3) & 1;

    float acc[4][4][4];
#pragma unroll
    for (int i = 0; i < 4; ++i)
#pragma unroll
        for (int j = 0; j < 4; ++j)
#pragma unroll
            for (int q = 0; q < 4; ++q) acc[i][j][q] = 0.f;

    uint32_t afrag[4][4];
    uint32_t bfrag[2][4];

    // prologue: stage 0
    load_stage(sbase, m0, n0, 0, tid);
    asm volatile("cp.async.commit_group;" ::: "memory");

    for (int it = 0; it < NITER; ++it) {
        asm volatile("cp.async.wait_group 0;" ::: "memory");
        __syncthreads();

        const uint32_t sA = sbase + (uint32_t)(it & 1) * STAGE_BYTES;
        const uint32_t sB = sA + A_BYTES;

        // Step-0 fragments FIRST, so they aren't queued behind the LDGSTS burst.
        frag_load(sA, sB, 0, arow_l, a_c, brow_l, b_c, wm, wn, afrag, bfrag);

        // prefetch next stage into the slot freed by iteration it-1
        if (it + 1 < NITER)
            load_stage(sbase + (uint32_t)((it + 1) & 1) * STAGE_BYTES, m0, n0, it + 1, tid);
        asm volatile("cp.async.commit_group;" ::: "memory");

#pragma unroll
        for (int s = 0; s < 8; ++s) {
            frag_mma(afrag, bfrag, acc);
            if (s < 7)
                frag_load(sA, sB, s + 1, arow_l, a_c, brow_l, b_c, wm, wn, afrag, bfrag);
        }
    }

    // epilogue: bias + float2 stores (warp tile 64x32)
    const int ncol = n0 + wn * 32 + (lane & 3) * 2;
    const int mrow = m0 + wm * 64 + (lane >> 2);
#pragma unroll
    for (int mi = 0; mi < 4; ++mi) {
        float* r0 = out + (size_t)(mrow + mi * 16) * OUT_F;
        float* r1 = r0 + 8 * OUT_F;
#pragma unroll
        for (int ni = 0; ni < 4; ++ni) {
            float2 bv = *reinterpret_cast<const float2*>(bias + ncol + ni * 8);
            float2 v0, v1;
            v0.x = acc[mi][ni][0] + bv.x;
            v0.y = acc[mi][ni][1] + bv.y;
            v1.x = acc[mi][ni][2] + bv.x;
            v1.y = acc[mi][ni][3] + bv.y;
            *reinterpret_cast<float2*>(r0 + ncol + ni * 8) = v0;
            *reinterpret_cast<float2*>(r1 + ncol + ni * 8) = v1;
        }
    }
}

// ---------------------------------------------------------- launch
extern "C" void kernel_launch(void* const* d_in, const int* in_sizes, int n_in,
                              void* d_out, int out_size) {
    const float* x    = (const float*)d_in[0];
    const int*   wq   = (const int*)d_in[1];
    const float* sw   = (const float*)d_in[2];
    const int*   perm = (const int*)d_in[3];   // int32 or int64 — detected on device
    const float* bias = (const float*)d_in[4];
    float* out = (float*)d_out;

    prep_kernel<<<4096 + MTOT, 256>>>(wq, sw, x, perm);

    cudaFuncSetAttribute(gemm_kernel, cudaFuncAttributeMaxDynamicSharedMemorySize, GEMM_SMEM);
    gemm_kernel<<<dim3(OUT_F / 128, MTOT / 256), 512, GEMM_SMEM>>>(bias, out);
}

// round 8
// speedup vs baseline: 1.1321x; 1.1321x over previous
#include <cuda_runtime.h>
#include <cuda_fp16.h>
#include <cstdint>

#define IN_F  4096
#define OUT_F 4096
#define MTOT  2048
#define NGRP  32          // IN_F / 128

// fp16 scratch (device globals: no allocation in kernel_launch)
__device__ __half g_wh[(size_t)OUT_F * IN_F];   // w_q * s_w, [o, k] K-major
__device__ __half g_xh[(size_t)MTOT  * IN_F];   // permuted x, [m, k] K-major

// ------------------------------------------------------------------ helpers
__device__ __forceinline__ uint32_t smem_u32(const void* p) {
    uint32_t a;
    asm("{ .reg .u64 t; cvta.to.shared.u64 t, %1; cvt.u32.u64 %0, t; }" : "=r"(a) : "l"(p));
    return a;
}

// 128B-row swizzle: XOR 16B-chunk index with row (bits 7..9 -> bits 4..6)
__device__ __forceinline__ uint32_t sw128(uint32_t off) { return off ^ ((off >> 3) & 0x70); }

__device__ __forceinline__ void cpa16(uint32_t dst, const void* src) {
    asm volatile("cp.async.cg.shared.global [%0], [%1], 16;" :: "r"(dst), "l"(src));
}

__device__ __forceinline__ void redadd(float* p, float v) {
    asm volatile("red.global.add.f32 [%0], %1;" :: "l"(p), "f"(v) : "memory");
}

#define LDSM4(r0, r1, r2, r3, addr) \
    asm volatile("ldmatrix.sync.aligned.m8n8.x4.shared.b16 {%0,%1,%2,%3}, [%4];" \
        : "=r"(r0), "=r"(r1), "=r"(r2), "=r"(r3) : "r"(addr))

#define MMA16816(d0, d1, d2, d3, a0, a1, a2, a3, b0, b1) \
    asm volatile("mma.sync.aligned.m16n8k16.row.col.f32.f16.f16.f32 " \
        "{%0,%1,%2,%3},{%4,%5,%6,%7},{%8,%9},{%0,%1,%2,%3};" \
        : "+f"(d0), "+f"(d1), "+f"(d2), "+f"(d3) \
        : "r"(a0), "r"(a1), "r"(a2), "r"(a3), "r"(b0), "r"(b1))

// ---------------------------------------------------------- fused prep
// blocks [0, 4096):            w-row o; w_q * s_w -> fp16, scales staged in smem
// blocks [4096, 6144):         x-row m; permute + fp32->fp16
// blocks [6144, 8192):         out-row m; prefill out = bias (atomic accumulation base)
__global__ void __launch_bounds__(256) prep_kernel(const int* __restrict__ wq,
                                                   const float* __restrict__ sw,
                                                   const float* __restrict__ x,
                                                   const int* __restrict__ perm32,
                                                   const float* __restrict__ bias,
                                                   float* __restrict__ out) {
    __shared__ float row[IN_F];          // x-branch row cache; w-branch uses first 32 floats
    __shared__ int is64s;
    const int tid = threadIdx.x;

    if (blockIdx.x >= 6144) {            // bias prefill
        const int m = blockIdx.x - 6144;
        const float4* bsrc = reinterpret_cast<const float4*>(bias);
        float4* dst = reinterpret_cast<float4*>(out + (size_t)m * OUT_F);
#pragma unroll
        for (int i = 0; i < 4; ++i)
            dst[tid + i * 256] = bsrc[tid + i * 256];
        return;
    }

    if (blockIdx.x < 4096) {
        const int o = blockIdx.x;
        if (tid < NGRP) row[tid] = sw[tid * OUT_F + o];
        __syncthreads();
        const float s = row[tid >> 3];                  // group = (tid*16)/128 = tid>>3
        const int k0 = tid * 16;
        const int4* p = reinterpret_cast<const int4*>(wq + (size_t)o * IN_F + k0);
        int4 w0 = p[0], w1 = p[1], w2 = p[2], w3 = p[3];
        uint4 v0, v1;
        {
            __half2 h0 = __floats2half2_rn(w0.x * s, w0.y * s);
            __half2 h1 = __floats2half2_rn(w0.z * s, w0.w * s);
            __half2 h2 = __floats2half2_rn(w1.x * s, w1.y * s);
            __half2 h3 = __floats2half2_rn(w1.z * s, w1.w * s);
            v0.x = *reinterpret_cast<uint32_t*>(&h0);
            v0.y = *reinterpret_cast<uint32_t*>(&h1);
            v0.z = *reinterpret_cast<uint32_t*>(&h2);
            v0.w = *reinterpret_cast<uint32_t*>(&h3);
        }
        {
            __half2 h0 = __floats2half2_rn(w2.x * s, w2.y * s);
            __half2 h1 = __floats2half2_rn(w2.z * s, w2.w * s);
            __half2 h2 = __floats2half2_rn(w3.x * s, w3.y * s);
            __half2 h3 = __floats2half2_rn(w3.z * s, w3.w * s);
            v1.x = *reinterpret_cast<uint32_t*>(&h0);
            v1.y = *reinterpret_cast<uint32_t*>(&h1);
            v1.z = *reinterpret_cast<uint32_t*>(&h2);
            v1.w = *reinterpret_cast<uint32_t*>(&h3);
        }
        uint4* dst = reinterpret_cast<uint4*>(g_wh + (size_t)o * IN_F + k0);
        dst[0] = v0;
        dst[1] = v1;
        return;
    }

    const int m = blockIdx.x - 4096;
    const float4* src = reinterpret_cast<const float4*>(x + (size_t)m * IN_F);
#pragma unroll
    for (int i = 0; i < 4; ++i)
        reinterpret_cast<float4*>(row)[tid + i * 256] = src[tid + i * 256];
    if (tid == 0) {
        // jnp int64 vs int32 detection: int64 LE => odd 32-bit words all zero.
        int acc = 0;
#pragma unroll
        for (int t = 1; t < 32; t += 2) acc |= perm32[t];
        is64s = (acc == 0) ? 1 : 0;
    }
    __syncthreads();
    const int sh = is64s;
    const int j0 = tid * 16;
    __half* dst = g_xh + (size_t)m * IN_F + j0;
#pragma unroll
    for (int h = 0; h < 2; ++h) {
        int jb = j0 + h * 8;
        float v[8];
#pragma unroll
        for (int i = 0; i < 8; ++i) v[i] = row[perm32[(jb + i) << sh]];
        __half2 p0 = __floats2half2_rn(v[0], v[1]);
        __half2 p1 = __floats2half2_rn(v[2], v[3]);
        __half2 p2 = __floats2half2_rn(v[4], v[5]);
        __half2 p3 = __floats2half2_rn(v[6], v[7]);
        uint4 u;
        u.x = *reinterpret_cast<uint32_t*>(&p0);
        u.y = *reinterpret_cast<uint32_t*>(&p1);
        u.z = *reinterpret_cast<uint32_t*>(&p2);
        u.w = *reinterpret_cast<uint32_t*>(&p3);
        *reinterpret_cast<uint4*>(dst + h * 8) = u;
    }
}

// ---------------------------------------------------------- GEMM: persistent chunk-balanced
// Tile 256(M) x 128(N) x 128(K-iter). 256 tiles x 32 k-iters = 8192 chunks spread evenly
// over 148 persistent CTAs (~55.35 each) -> no wave tail. A tile straddles <=1 CTA
// boundary; partial tiles accumulate via red.global.add.f32 into bias-prefilled out,
// full tiles store acc+bias directly (sole writer).
// Within-tile: 8 warps 4(M)x2(N), warp tile 64x64, 2-stage cp.async, 192KB smem.
static constexpr int NITER       = IN_F / 128;        // 32 chunks per tile
static constexpr uint32_t TOTAL_CHUNKS = 256u * 32u;  // 8192
static constexpr uint32_t NCTA   = 148;
static constexpr uint32_t A_BYTES     = 65536;        // 2 x 32KB (kh halves)
static constexpr uint32_t STAGE_BYTES = 98304;
static constexpr uint32_t GEMM_SMEM   = 2 * STAGE_BYTES;  // 196608

__device__ __forceinline__ void load_stage(uint32_t sb, int m0, int n0, int j, int tid) {
    const int k0 = j * 128;
#pragma unroll
    for (int kh = 0; kh < 2; ++kh) {
#pragma unroll
        for (int c = 0; c < 8; ++c) {             // A half: 256 rows x 8 chunks of 16B
            int idx = tid + c * 256;
            int row = idx >> 3, ch = idx & 7;
            cpa16(sb + (uint32_t)kh * 32768u + sw128((uint32_t)row * 128u + (uint32_t)ch * 16u),
                  g_xh + (size_t)(m0 + row) * IN_F + k0 + kh * 64 + ch * 8);
        }
#pragma unroll
        for (int c = 0; c < 4; ++c) {             // B half: 128 rows x 8 chunks
            int idx = tid + c * 256;
            int row = idx >> 3, ch = idx & 7;
            cpa16(sb + A_BYTES + (uint32_t)kh * 16384u + sw128((uint32_t)row * 128u + (uint32_t)ch * 16u),
                  g_wh + (size_t)(n0 + row) * IN_F + k0 + kh * 64 + ch * 8);
        }
    }
}

// Fragments for k-step s (s in 0..7: kh = s>>2, ks = s&3); warp tile 64(M) x 64(N)
__device__ __forceinline__ void frag_load(uint32_t sA, uint32_t sB, int s,
                                          int arow_l, int a_c, int brow_l, int b_c,
                                          int wm, int wn, uint32_t a[4][4], uint32_t b[4][4]) {
    const uint32_t aBase = sA + (uint32_t)(s >> 2) * 32768u;
    const uint32_t bBase = sB + (uint32_t)(s >> 2) * 16384u;
    const int ks = s & 3;
#pragma unroll
    for (int mi = 0; mi < 4; ++mi) {
        uint32_t off = (uint32_t)((wm * 64 + mi * 16 + arow_l) * 128 + (ks * 2 + a_c) * 16);
        LDSM4(a[mi][0], a[mi][1], a[mi][2], a[mi][3], aBase + sw128(off));
    }
#pragma unroll
    for (int nb = 0; nb < 4; ++nb) {
        uint32_t off = (uint32_t)((wn * 64 + nb * 16 + brow_l) * 128 + (ks * 2 + b_c) * 16);
        LDSM4(b[nb][0], b[nb][1], b[nb][2], b[nb][3], bBase + sw128(off));
    }
}

__device__ __forceinline__ void frag_mma(const uint32_t a[4][4], const uint32_t b[4][4],
                                         float acc[4][8][4]) {
#pragma unroll
    for (int mi = 0; mi < 4; ++mi)
#pragma unroll
        for (int ni = 0; ni < 8; ++ni) {
            uint32_t b0 = b[ni >> 1][(ni & 1) * 2];
            uint32_t b1 = b[ni >> 1][(ni & 1) * 2 + 1];
            MMA16816(acc[mi][ni][0], acc[mi][ni][1], acc[mi][ni][2], acc[mi][ni][3],
                     a[mi][0], a[mi][1], a[mi][2], a[mi][3], b0, b1);
        }
}

__global__ void __launch_bounds__(256, 1) gemm_kernel(const float* __restrict__ bias,
                                                      float* __restrict__ out) {
    extern __shared__ char smem[];
    const uint32_t sbase = smem_u32(smem);
    const int tid  = threadIdx.x;
    const int lane = tid & 31, wid = tid >> 5;
    const int wm = wid & 3, wn = wid >> 2;        // 4 x 2 warp grid
    const int arow_l = (lane & 7) + ((lane >> 3) & 1) * 8;
    const int a_c    = lane >> 4;
    const int brow_l = (lane & 7) + ((lane >> 4) & 1) * 8;
    const int b_c    = (lane >> 3) & 1;

    const uint32_t c = blockIdx.x;
    uint32_t start   = (c * TOTAL_CHUNKS) / NCTA;
    const uint32_t end = ((c + 1) * TOTAL_CHUNKS) / NCTA;
    uint32_t t = start >> 5;                      // current tile

    uint32_t afrag[2][4][4], bfrag[2][4][4];

    while (start < end) {
        const uint32_t ka = start & 31u;
        const uint32_t rem = end - (t << 5);
        const uint32_t kb = rem < 32u ? rem : 32u;
        const int m0 = (int)(t >> 5) * 256;       // 8 m-tiles x 32 n-tiles, n fastest
        const int n0 = (int)(t & 31u) * 128;

        float acc[4][8][4];
#pragma unroll
        for (int i = 0; i < 4; ++i)
#pragma unroll
            for (int j = 0; j < 8; ++j)
#pragma unroll
                for (int q = 0; q < 4; ++q) acc[i][j][q] = 0.f;

        __syncthreads();   // smem slots free (previous tile fully consumed by all warps)
        load_stage(sbase + (ka & 1u) * STAGE_BYTES, m0, n0, (int)ka, tid);
        asm volatile("cp.async.commit_group;" ::: "memory");

        for (uint32_t it = ka; it < kb; ++it) {
            asm volatile("cp.async.wait_group 0;" ::: "memory");
            __syncthreads();

            const uint32_t sA = sbase + (it & 1u) * STAGE_BYTES;
            const uint32_t sB = sA + A_BYTES;

            frag_load(sA, sB, 0, arow_l, a_c, brow_l, b_c, wm, wn, afrag[0], bfrag[0]);

            if (it + 1 < kb)
                load_stage(sbase + ((it + 1) & 1u) * STAGE_BYTES, m0, n0, (int)(it + 1), tid);
            asm volatile("cp.async.commit_group;" ::: "memory");

#pragma unroll
            for (int s = 0; s < 8; ++s) {
                if (s < 7)
                    frag_load(sA, sB, s + 1, arow_l, a_c, brow_l, b_c, wm, wn,
                              afrag[(s + 1) & 1], bfrag[(s + 1) & 1]);
                frag_mma(afrag[s & 1], bfrag[s & 1], acc);
            }
        }

        // epilogue
        const int ncol = n0 + wn * 64 + (lane & 3) * 2;
        const int mrow = m0 + wm * 64 + (lane >> 2);
        const bool full = (ka == 0u && kb == 32u);
        if (full) {
#pragma unroll
            for (int mi = 0; mi < 4; ++mi) {
                float* r0 = out + (size_t)(mrow + mi * 16) * OUT_F;
                float* r1 = r0 + 8 * OUT_F;
#pragma unroll
                for (int ni = 0; ni < 8; ++ni) {
                    float2 bv = *reinterpret_cast<const float2*>(bias + ncol + ni * 8);
                    float2 v0, v1;
                    v0.x = acc[mi][ni][0] + bv.x;
                    v0.y = acc[mi][ni][1] + bv.y;
                    v1.x = acc[mi][ni][2] + bv.x;
                    v1.y = acc[mi][ni][3] + bv.y;
                    *reinterpret_cast<float2*>(r0 + ncol + ni * 8) = v0;
                    *reinterpret_cast<float2*>(r1 + ncol + ni * 8) = v1;
                }
            }
        } else {
#pragma unroll
            for (int mi = 0; mi < 4; ++mi) {
                float* r0 = out + (size_t)(mrow + mi * 16) * OUT_F;
                float* r1 = r0 + 8 * OUT_F;
#pragma unroll
                for (int ni = 0; ni < 8; ++ni) {
                    redadd(r0 + ncol + ni * 8,     acc[mi][ni][0]);
                    redadd(r0 + ncol + ni * 8 + 1, acc[mi][ni][1]);
                    redadd(r1 + ncol + ni * 8,     acc[mi][ni][2]);
                    redadd(r1 + ncol + ni * 8 + 1, acc[mi][ni][3]);
                }
            }
        }

        start = (t << 5) + kb;
        ++t;
    }
}

// ---------------------------------------------------------- launch
extern "C" void kernel_launch(void* const* d_in, const int* in_sizes, int n_in,
                              void* d_out, int out_size) {
    const float* x    = (const float*)d_in[0];
    const int*   wq   = (const int*)d_in[1];
    const float* sw   = (const float*)d_in[2];
    const int*   perm = (const int*)d_in[3];   // int32 or int64 — detected on device
    const float* bias = (const float*)d_in[4];
    float* out = (float*)d_out;

    prep_kernel<<<4096 + MTOT + MTOT, 256>>>(wq, sw, x, perm, bias, out);

    cudaFuncSetAttribute(gemm_kernel, cudaFuncAttributeMaxDynamicSharedMemorySize, GEMM_SMEM);
    gemm_kernel<<<NCTA, 256, GEMM_SMEM>>>(bias, out);
}

// round 9
// speedup vs baseline: 1.1412x; 1.0080x over previous
#include <cuda_runtime.h>
#include <cuda_fp16.h>
#include <cstdint>

#define IN_F  4096
#define OUT_F 4096
#define MTOT  2048
#define NGRP  32          // IN_F / 128

// fp16 scratch (device globals: no allocation in kernel_launch)
__device__ __half g_wh[(size_t)OUT_F * IN_F];   // w_q * s_w, [o, k] K-major
__device__ __half g_xh[(size_t)MTOT  * IN_F];   // permuted x, [m, k] K-major

// ------------------------------------------------------------------ helpers
__device__ __forceinline__ uint32_t smem_u32(const void* p) {
    uint32_t a;
    asm("{ .reg .u64 t; cvta.to.shared.u64 t, %1; cvt.u32.u64 %0, t; }" : "=r"(a) : "l"(p));
    return a;
}

// 128B-row swizzle: XOR 16B-chunk index with row (bits 7..9 -> bits 4..6)
__device__ __forceinline__ uint32_t sw128(uint32_t off) { return off ^ ((off >> 3) & 0x70); }

__device__ __forceinline__ void cpa16(uint32_t dst, const void* src) {
    asm volatile("cp.async.cg.shared.global [%0], [%1], 16;" :: "r"(dst), "l"(src));
}

__device__ __forceinline__ void redadd(float* p, float v) {
    asm volatile("red.global.add.f32 [%0], %1;" :: "l"(p), "f"(v) : "memory");
}

#define LDSM4(r0, r1, r2, r3, addr) \
    asm volatile("ldmatrix.sync.aligned.m8n8.x4.shared.b16 {%0,%1,%2,%3}, [%4];" \
        : "=r"(r0), "=r"(r1), "=r"(r2), "=r"(r3) : "r"(addr))

#define MMA16816(d0, d1, d2, d3, a0, a1, a2, a3, b0, b1) \
    asm volatile("mma.sync.aligned.m16n8k16.row.col.f32.f16.f16.f32 " \
        "{%0,%1,%2,%3},{%4,%5,%6,%7},{%8,%9},{%0,%1,%2,%3};" \
        : "+f"(d0), "+f"(d1), "+f"(d2), "+f"(d3) \
        : "r"(a0), "r"(a1), "r"(a2), "r"(a3), "r"(b0), "r"(b1))

// ---------------------------------------------------------- fused prep
// blocks [0, 4096):            w-row o; w_q * s_w -> fp16, scales staged in smem
// blocks [4096, 6144):         x-row m; permute + fp32->fp16
// blocks [6144, 8192):         out-row m; prefill out = bias (atomic accumulation base)
__global__ void __launch_bounds__(256) prep_kernel(const int* __restrict__ wq,
                                                   const float* __restrict__ sw,
                                                   const float* __restrict__ x,
                                                   const int* __restrict__ perm32,
                                                   const float* __restrict__ bias,
                                                   float* __restrict__ out) {
    __shared__ float row[IN_F];          // x-branch row cache; w-branch uses first 32 floats
    __shared__ int is64s;
    const int tid = threadIdx.x;

    if (blockIdx.x >= 6144) {            // bias prefill
        const int m = blockIdx.x - 6144;
        const float4* bsrc = reinterpret_cast<const float4*>(bias);
        float4* dst = reinterpret_cast<float4*>(out + (size_t)m * OUT_F);
#pragma unroll
        for (int i = 0; i < 4; ++i)
            dst[tid + i * 256] = bsrc[tid + i * 256];
        return;
    }

    if (blockIdx.x < 4096) {
        const int o = blockIdx.x;
        if (tid < NGRP) row[tid] = sw[tid * OUT_F + o];
        __syncthreads();
        const float s = row[tid >> 3];                  // group = (tid*16)/128 = tid>>3
        const int k0 = tid * 16;
        const int4* p = reinterpret_cast<const int4*>(wq + (size_t)o * IN_F + k0);
        int4 w0 = p[0], w1 = p[1], w2 = p[2], w3 = p[3];
        uint4 v0, v1;
        {
            __half2 h0 = __floats2half2_rn(w0.x * s, w0.y * s);
            __half2 h1 = __floats2half2_rn(w0.z * s, w0.w * s);
            __half2 h2 = __floats2half2_rn(w1.x * s, w1.y * s);
            __half2 h3 = __floats2half2_rn(w1.z * s, w1.w * s);
            v0.x = *reinterpret_cast<uint32_t*>(&h0);
            v0.y = *reinterpret_cast<uint32_t*>(&h1);
            v0.z = *reinterpret_cast<uint32_t*>(&h2);
            v0.w = *reinterpret_cast<uint32_t*>(&h3);
        }
        {
            __half2 h0 = __floats2half2_rn(w2.x * s, w2.y * s);
            __half2 h1 = __floats2half2_rn(w2.z * s, w2.w * s);
            __half2 h2 = __floats2half2_rn(w3.x * s, w3.y * s);
            __half2 h3 = __floats2half2_rn(w3.z * s, w3.w * s);
            v1.x = *reinterpret_cast<uint32_t*>(&h0);
            v1.y = *reinterpret_cast<uint32_t*>(&h1);
            v1.z = *reinterpret_cast<uint32_t*>(&h2);
            v1.w = *reinterpret_cast<uint32_t*>(&h3);
        }
        uint4* dst = reinterpret_cast<uint4*>(g_wh + (size_t)o * IN_F + k0);
        dst[0] = v0;
        dst[1] = v1;
        return;
    }

    const int m = blockIdx.x - 4096;
    const float4* src = reinterpret_cast<const float4*>(x + (size_t)m * IN_F);
#pragma unroll
    for (int i = 0; i < 4; ++i)
        reinterpret_cast<float4*>(row)[tid + i * 256] = src[tid + i * 256];
    if (tid == 0) {
        // jnp int64 vs int32 detection: int64 LE => odd 32-bit words all zero.
        int acc = 0;
#pragma unroll
        for (int t = 1; t < 32; t += 2) acc |= perm32[t];
        is64s = (acc == 0) ? 1 : 0;
    }
    __syncthreads();
    const int sh = is64s;
    const int j0 = tid * 16;
    __half* dst = g_xh + (size_t)m * IN_F + j0;
#pragma unroll
    for (int h = 0; h < 2; ++h) {
        int jb = j0 + h * 8;
        float v[8];
#pragma unroll
        for (int i = 0; i < 8; ++i) v[i] = row[perm32[(jb + i) << sh]];
        __half2 p0 = __floats2half2_rn(v[0], v[1]);
        __half2 p1 = __floats2half2_rn(v[2], v[3]);
        __half2 p2 = __floats2half2_rn(v[4], v[5]);
        __half2 p3 = __floats2half2_rn(v[6], v[7]);
        uint4 u;
        u.x = *reinterpret_cast<uint32_t*>(&p0);
        u.y = *reinterpret_cast<uint32_t*>(&p1);
        u.z = *reinterpret_cast<uint32_t*>(&p2);
        u.w = *reinterpret_cast<uint32_t*>(&p3);
        *reinterpret_cast<uint4*>(dst + h * 8) = u;
    }
}

// ---------------------------------------------------------- GEMM: persistent, flat chunk loop
// Tile 256(M) x 128(N), chunk = one BK=128 k-iter of a tile; 8192 chunks over 148 CTAs.
// The chunk loop runs the 2-stage cp.async pipeline CONTINUOUSLY across tile boundaries:
// prefetch of chunk c+1 (possibly next tile) overlaps compute of c, and the register-only
// epilogue overlaps the in-flight stage load. Partial tiles accumulate via red.global
// into bias-prefilled out; full tiles store acc+bias directly.
static constexpr uint32_t TOTAL_CHUNKS = 256u * 32u;  // 8192
static constexpr uint32_t NCTA   = 148;
static constexpr uint32_t A_BYTES     = 65536;        // 2 x 32KB (kh halves)
static constexpr uint32_t STAGE_BYTES = 98304;
static constexpr uint32_t GEMM_SMEM   = 2 * STAGE_BYTES;  // 196608

__device__ __forceinline__ void load_chunk(uint32_t sb, uint32_t chunk, int tid) {
    const uint32_t t = chunk >> 5;
    const int m0 = (int)(t >> 5) * 256;               // 8 m-tiles x 32 n-tiles, n fastest
    const int n0 = (int)(t & 31u) * 128;
    const int k0 = (int)(chunk & 31u) * 128;
#pragma unroll
    for (int kh = 0; kh < 2; ++kh) {
#pragma unroll
        for (int c = 0; c < 8; ++c) {             // A half: 256 rows x 8 chunks of 16B
            int idx = tid + c * 256;
            int row = idx >> 3, ch = idx & 7;
            cpa16(sb + (uint32_t)kh * 32768u + sw128((uint32_t)row * 128u + (uint32_t)ch * 16u),
                  g_xh + (size_t)(m0 + row) * IN_F + k0 + kh * 64 + ch * 8);
        }
#pragma unroll
        for (int c = 0; c < 4; ++c) {             // B half: 128 rows x 8 chunks
            int idx = tid + c * 256;
            int row = idx >> 3, ch = idx & 7;
            cpa16(sb + A_BYTES + (uint32_t)kh * 16384u + sw128((uint32_t)row * 128u + (uint32_t)ch * 16u),
                  g_wh + (size_t)(n0 + row) * IN_F + k0 + kh * 64 + ch * 8);
        }
    }
}

// Fragments for k-step s (s in 0..7: kh = s>>2, ks = s&3); warp tile 64(M) x 64(N)
__device__ __forceinline__ void frag_load(uint32_t sA, uint32_t sB, int s,
                                          int arow_l, int a_c, int brow_l, int b_c,
                                          int wm, int wn, uint32_t a[4][4], uint32_t b[4][4]) {
    const uint32_t aBase = sA + (uint32_t)(s >> 2) * 32768u;
    const uint32_t bBase = sB + (uint32_t)(s >> 2) * 16384u;
    const int ks = s & 3;
#pragma unroll
    for (int mi = 0; mi < 4; ++mi) {
        uint32_t off = (uint32_t)((wm * 64 + mi * 16 + arow_l) * 128 + (ks * 2 + a_c) * 16);
        LDSM4(a[mi][0], a[mi][1], a[mi][2], a[mi][3], aBase + sw128(off));
    }
#pragma unroll
    for (int nb = 0; nb < 4; ++nb) {
        uint32_t off = (uint32_t)((wn * 64 + nb * 16 + brow_l) * 128 + (ks * 2 + b_c) * 16);
        LDSM4(b[nb][0], b[nb][1], b[nb][2], b[nb][3], bBase + sw128(off));
    }
}

__device__ __forceinline__ void frag_mma(const uint32_t a[4][4], const uint32_t b[4][4],
                                         float acc[4][8][4]) {
#pragma unroll
    for (int mi = 0; mi < 4; ++mi)
#pragma unroll
        for (int ni = 0; ni < 8; ++ni) {
            uint32_t b0 = b[ni >> 1][(ni & 1) * 2];
            uint32_t b1 = b[ni >> 1][(ni & 1) * 2 + 1];
            MMA16816(acc[mi][ni][0], acc[mi][ni][1], acc[mi][ni][2], acc[mi][ni][3],
                     a[mi][0], a[mi][1], a[mi][2], a[mi][3], b0, b1);
        }
}

__global__ void __launch_bounds__(256, 1) gemm_kernel(const float* __restrict__ bias,
                                                      float* __restrict__ out) {
    extern __shared__ char smem[];
    const uint32_t sbase = smem_u32(smem);
    const int tid  = threadIdx.x;
    const int lane = tid & 31, wid = tid >> 5;
    const int wm = wid & 3, wn = wid >> 2;        // 4 x 2 warp grid
    const int arow_l = (lane & 7) + ((lane >> 3) & 1) * 8;
    const int a_c    = lane >> 4;
    const int brow_l = (lane & 7) + ((lane >> 4) & 1) * 8;
    const int b_c    = (lane >> 3) & 1;

    const uint32_t cta = blockIdx.x;
    const uint32_t start = (cta * TOTAL_CHUNKS) / NCTA;
    const uint32_t end   = ((cta + 1) * TOTAL_CHUNKS) / NCTA;

    float acc[4][8][4];
#pragma unroll
    for (int i = 0; i < 4; ++i)
#pragma unroll
        for (int j = 0; j < 8; ++j)
#pragma unroll
            for (int q = 0; q < 4; ++q) acc[i][j][q] = 0.f;

    uint32_t afrag[2][4][4], bfrag[2][4][4];
    uint32_t seg_first = start & 31u;             // first k-iter of current tile segment

    load_chunk(sbase + (start & 1u) * STAGE_BYTES, start, tid);
    asm volatile("cp.async.commit_group;" ::: "memory");

    for (uint32_t ch = start; ch < end; ++ch) {
        asm volatile("cp.async.wait_group 0;" ::: "memory");
        __syncthreads();

        const uint32_t sA = sbase + (ch & 1u) * STAGE_BYTES;
        const uint32_t sB = sA + A_BYTES;

        // Step-0 fragments FIRST, so they aren't queued behind the LDGSTS burst.
        frag_load(sA, sB, 0, arow_l, a_c, brow_l, b_c, wm, wn, afrag[0], bfrag[0]);

        // prefetch next chunk (possibly next tile) into the other buffer
        if (ch + 1 < end)
            load_chunk(sbase + ((ch + 1) & 1u) * STAGE_BYTES, ch + 1, tid);
        asm volatile("cp.async.commit_group;" ::: "memory");

#pragma unroll
        for (int s = 0; s < 8; ++s) {
            if (s < 7)
                frag_load(sA, sB, s + 1, arow_l, a_c, brow_l, b_c, wm, wn,
                          afrag[(s + 1) & 1], bfrag[(s + 1) & 1]);
            frag_mma(afrag[s & 1], bfrag[s & 1], acc);
        }

        const uint32_t kidx = ch & 31u;
        const bool tile_done = (kidx == 31u) || (ch + 1 == end);
        if (tile_done) {
            // epilogue for tile ch>>5 (register-only; overlaps next chunk's cp.async)
            const uint32_t t = ch >> 5;
            const int n0 = (int)(t & 31u) * 128;
            const int m0 = (int)(t >> 5) * 256;
            const int ncol = n0 + wn * 64 + (lane & 3) * 2;
            const int mrow = m0 + wm * 64 + (lane >> 2);
            const bool full = (seg_first == 0u && kidx == 31u);
            if (full) {
#pragma unroll
                for (int mi = 0; mi < 4; ++mi) {
                    float* r0 = out + (size_t)(mrow + mi * 16) * OUT_F;
                    float* r1 = r0 + 8 * OUT_F;
#pragma unroll
                    for (int ni = 0; ni < 8; ++ni) {
                        float2 bv = *reinterpret_cast<const float2*>(bias + ncol + ni * 8);
                        float2 v0, v1;
                        v0.x = acc[mi][ni][0] + bv.x;
                        v0.y = acc[mi][ni][1] + bv.y;
                        v1.x = acc[mi][ni][2] + bv.x;
                        v1.y = acc[mi][ni][3] + bv.y;
                        *reinterpret_cast<float2*>(r0 + ncol + ni * 8) = v0;
                        *reinterpret_cast<float2*>(r1 + ncol + ni * 8) = v1;
                    }
                }
            } else {
#pragma unroll
                for (int mi = 0; mi < 4; ++mi) {
                    float* r0 = out + (size_t)(mrow + mi * 16) * OUT_F;
                    float* r1 = r0 + 8 * OUT_F;
#pragma unroll
                    for (int ni = 0; ni < 8; ++ni) {
                        redadd(r0 + ncol + ni * 8,     acc[mi][ni][0]);
                        redadd(r0 + ncol + ni * 8 + 1, acc[mi][ni][1]);
                        redadd(r1 + ncol + ni * 8,     acc[mi][ni][2]);
                        redadd(r1 + ncol + ni * 8 + 1, acc[mi][ni][3]);
                    }
                }
            }
#pragma unroll
            for (int i = 0; i < 4; ++i)
#pragma unroll
                for (int j = 0; j < 8; ++j)
#pragma unroll
                    for (int q = 0; q < 4; ++q) acc[i][j][q] = 0.f;
            seg_first = 0u;
        }
    }
}

// ---------------------------------------------------------- launch
extern "C" void kernel_launch(void* const* d_in, const int* in_sizes, int n_in,
                              void* d_out, int out_size) {
    const float* x    = (const float*)d_in[0];
    const int*   wq   = (const int*)d_in[1];
    const float* sw   = (const float*)d_in[2];
    const int*   perm = (const int*)d_in[3];   // int32 or int64 — detected on device
    const float* bias = (const float*)d_in[4];
    float* out = (float*)d_out;

    prep_kernel<<<4096 + MTOT + MTOT, 256>>>(wq, sw, x, perm, bias, out);

    cudaFuncSetAttribute(gemm_kernel, cudaFuncAttributeMaxDynamicSharedMemorySize, GEMM_SMEM);
    gemm_kernel<<<NCTA, 256, GEMM_SMEM>>>(bias, out);
}

// round 10
// speedup vs baseline: 1.1414x; 1.0002x over previous
#include <cuda_runtime.h>
#include <cuda_fp16.h>
#include <cstdint>

#define IN_F  4096
#define OUT_F 4096
#define MTOT  2048
#define NGRP  32          // IN_F / 128

// fp16 scratch (device globals: no allocation in kernel_launch)
__device__ __half g_wh[(size_t)OUT_F * IN_F];   // w_q * s_w, [o, k] K-major
__device__ __half g_xh[(size_t)MTOT  * IN_F];   // permuted x, [m, k] K-major

// ------------------------------------------------------------------ helpers
__device__ __forceinline__ uint32_t smem_u32(const void* p) {
    uint32_t a;
    asm("{ .reg .u64 t; cvta.to.shared.u64 t, %1; cvt.u32.u64 %0, t; }" : "=r"(a) : "l"(p));
    return a;
}

// 128B-row swizzle: XOR 16B-chunk index with row (bits 7..9 -> bits 4..6)
__device__ __forceinline__ uint32_t sw128(uint32_t off) { return off ^ ((off >> 3) & 0x70); }

__device__ __forceinline__ void cpa16(uint32_t dst, const void* src) {
    asm volatile("cp.async.cg.shared.global [%0], [%1], 16;" :: "r"(dst), "l"(src));
}

__device__ __forceinline__ void redadd(float* p, float v) {
    asm volatile("red.global.add.f32 [%0], %1;" :: "l"(p), "f"(v) : "memory");
}

#define LDSM4(r0, r1, r2, r3, addr) \
    asm volatile("ldmatrix.sync.aligned.m8n8.x4.shared.b16 {%0,%1,%2,%3}, [%4];" \
        : "=r"(r0), "=r"(r1), "=r"(r2), "=r"(r3) : "r"(addr))

#define MMA16816(d0, d1, d2, d3, a0, a1, a2, a3, b0, b1) \
    asm volatile("mma.sync.aligned.m16n8k16.row.col.f32.f16.f16.f32 " \
        "{%0,%1,%2,%3},{%4,%5,%6,%7},{%8,%9},{%0,%1,%2,%3};" \
        : "+f"(d0), "+f"(d1), "+f"(d2), "+f"(d3) \
        : "r"(a0), "r"(a1), "r"(a2), "r"(a3), "r"(b0), "r"(b1))

static constexpr uint32_t TOTAL_CHUNKS = 256u * 32u;  // 8192
static constexpr uint32_t NCTA   = 148;

// ---------------------------------------------------------- fused prep
// blocks [0, 4096):       w-row o; w_q * s_w -> fp16 (streaming hints)
// blocks [4096, 6144):    x-row m; permute + fp32->fp16
// blocks [6144, 6291):    boundary c = bid-6144+1; prefill bias into SPLIT tiles only
__global__ void __launch_bounds__(256) prep_kernel(const int* __restrict__ wq,
                                                   const float* __restrict__ sw,
                                                   const float* __restrict__ x,
                                                   const int* __restrict__ perm32,
                                                   const float* __restrict__ bias,
                                                   float* __restrict__ out) {
    __shared__ float row[IN_F];          // x-branch row cache; w-branch uses first 32 floats
    __shared__ int is64s;
    const int tid = threadIdx.x;

    if (blockIdx.x >= 6144) {            // split-tile bias prefill
        const uint32_t c = blockIdx.x - 6144u + 1u;              // 1..147
        const uint32_t s = (c * TOTAL_CHUNKS) / NCTA;            // CTA c's start chunk
        if ((s & 31u) == 0u) return;                             // boundary on tile edge: not split
        const uint32_t t = s >> 5;
        const int m0 = (int)(t >> 5) * 256, n0 = (int)(t & 31u) * 128;
        if (tid < 128) row[tid] = bias[n0 + tid];
        __syncthreads();
#pragma unroll 4
        for (int it = 0; it < 32; ++it) {
            int idx = tid + it * 256;
            int r = idx >> 5, c4 = idx & 31;                     // 32 float4 per row
            float4 v = make_float4(row[c4 * 4], row[c4 * 4 + 1], row[c4 * 4 + 2], row[c4 * 4 + 3]);
            __stcs(reinterpret_cast<float4*>(out + (size_t)(m0 + r) * OUT_F + n0) + c4, v);
        }
        return;
    }

    if (blockIdx.x < 4096) {
        const int o = blockIdx.x;
        if (tid < NGRP) row[tid] = sw[tid * OUT_F + o];
        __syncthreads();
        const float s = row[tid >> 3];                  // group = (tid*16)/128 = tid>>3
        const int k0 = tid * 16;
        const int4* p = reinterpret_cast<const int4*>(wq + (size_t)o * IN_F + k0);
        int4 w0 = __ldcs(p), w1 = __ldcs(p + 1), w2 = __ldcs(p + 2), w3 = __ldcs(p + 3);
        uint4 v0, v1;
        {
            __half2 h0 = __floats2half2_rn(w0.x * s, w0.y * s);
            __half2 h1 = __floats2half2_rn(w0.z * s, w0.w * s);
            __half2 h2 = __floats2half2_rn(w1.x * s, w1.y * s);
            __half2 h3 = __floats2half2_rn(w1.z * s, w1.w * s);
            v0.x = *reinterpret_cast<uint32_t*>(&h0);
            v0.y = *reinterpret_cast<uint32_t*>(&h1);
            v0.z = *reinterpret_cast<uint32_t*>(&h2);
            v0.w = *reinterpret_cast<uint32_t*>(&h3);
        }
        {
            __half2 h0 = __floats2half2_rn(w2.x * s, w2.y * s);
            __half2 h1 = __floats2half2_rn(w2.z * s, w2.w * s);
            __half2 h2 = __floats2half2_rn(w3.x * s, w3.y * s);
            __half2 h3 = __floats2half2_rn(w3.z * s, w3.w * s);
            v1.x = *reinterpret_cast<uint32_t*>(&h0);
            v1.y = *reinterpret_cast<uint32_t*>(&h1);
            v1.z = *reinterpret_cast<uint32_t*>(&h2);
            v1.w = *reinterpret_cast<uint32_t*>(&h3);
        }
        uint4* dst = reinterpret_cast<uint4*>(g_wh + (size_t)o * IN_F + k0);
        __stcs(dst, v0);
        __stcs(dst + 1, v1);
        return;
    }

    const int m = blockIdx.x - 4096;
    const float4* src = reinterpret_cast<const float4*>(x + (size_t)m * IN_F);
#pragma unroll
    for (int i = 0; i < 4; ++i)
        reinterpret_cast<float4*>(row)[tid + i * 256] = __ldcs(src + tid + i * 256);
    if (tid == 0) {
        // jnp int64 vs int32 detection: int64 LE => odd 32-bit words all zero.
        int acc = 0;
#pragma unroll
        for (int t = 1; t < 32; t += 2) acc |= perm32[t];
        is64s = (acc == 0) ? 1 : 0;
    }
    __syncthreads();
    const int sh = is64s;
    const int j0 = tid * 16;
    __half* dst = g_xh + (size_t)m * IN_F + j0;
#pragma unroll
    for (int h = 0; h < 2; ++h) {
        int jb = j0 + h * 8;
        float v[8];
#pragma unroll
        for (int i = 0; i < 8; ++i) v[i] = row[perm32[(jb + i) << sh]];
        __half2 p0 = __floats2half2_rn(v[0], v[1]);
        __half2 p1 = __floats2half2_rn(v[2], v[3]);
        __half2 p2 = __floats2half2_rn(v[4], v[5]);
        __half2 p3 = __floats2half2_rn(v[6], v[7]);
        uint4 u;
        u.x = *reinterpret_cast<uint32_t*>(&p0);
        u.y = *reinterpret_cast<uint32_t*>(&p1);
        u.z = *reinterpret_cast<uint32_t*>(&p2);
        u.w = *reinterpret_cast<uint32_t*>(&p3);
        __stcs(reinterpret_cast<uint4*>(dst + h * 8), u);
    }
}

// ---------------------------------------------------------- GEMM: persistent, flat chunk loop
// (unchanged from R9 — at the mma.sync plateau)
static constexpr uint32_t A_BYTES     = 65536;        // 2 x 32KB (kh halves)
static constexpr uint32_t STAGE_BYTES = 98304;
static constexpr uint32_t GEMM_SMEM   = 2 * STAGE_BYTES;  // 196608

__device__ __forceinline__ void load_chunk(uint32_t sb, uint32_t chunk, int tid) {
    const uint32_t t = chunk >> 5;
    const int m0 = (int)(t >> 5) * 256;               // 8 m-tiles x 32 n-tiles, n fastest
    const int n0 = (int)(t & 31u) * 128;
    const int k0 = (int)(chunk & 31u) * 128;
#pragma unroll
    for (int kh = 0; kh < 2; ++kh) {
#pragma unroll
        for (int c = 0; c < 8; ++c) {             // A half: 256 rows x 8 chunks of 16B
            int idx = tid + c * 256;
            int row = idx >> 3, ch = idx & 7;
            cpa16(sb + (uint32_t)kh * 32768u + sw128((uint32_t)row * 128u + (uint32_t)ch * 16u),
                  g_xh + (size_t)(m0 + row) * IN_F + k0 + kh * 64 + ch * 8);
        }
#pragma unroll
        for (int c = 0; c < 4; ++c) {             // B half: 128 rows x 8 chunks
            int idx = tid + c * 256;
            int row = idx >> 3, ch = idx & 7;
            cpa16(sb + A_BYTES + (uint32_t)kh * 16384u + sw128((uint32_t)row * 128u + (uint32_t)ch * 16u),
                  g_wh + (size_t)(n0 + row) * IN_F + k0 + kh * 64 + ch * 8);
        }
    }
}

// Fragments for k-step s (s in 0..7: kh = s>>2, ks = s&3); warp tile 64(M) x 64(N)
__device__ __forceinline__ void frag_load(uint32_t sA, uint32_t sB, int s,
                                          int arow_l, int a_c, int brow_l, int b_c,
                                          int wm, int wn, uint32_t a[4][4], uint32_t b[4][4]) {
    const uint32_t aBase = sA + (uint32_t)(s >> 2) * 32768u;
    const uint32_t bBase = sB + (uint32_t)(s >> 2) * 16384u;
    const int ks = s & 3;
#pragma unroll
    for (int mi = 0; mi < 4; ++mi) {
        uint32_t off = (uint32_t)((wm * 64 + mi * 16 + arow_l) * 128 + (ks * 2 + a_c) * 16);
        LDSM4(a[mi][0], a[mi][1], a[mi][2], a[mi][3], aBase + sw128(off));
    }
#pragma unroll
    for (int nb = 0; nb < 4; ++nb) {
        uint32_t off = (uint32_t)((wn * 64 + nb * 16 + brow_l) * 128 + (ks * 2 + b_c) * 16);
        LDSM4(b[nb][0], b[nb][1], b[nb][2], b[nb][3], bBase + sw128(off));
    }
}

__device__ __forceinline__ void frag_mma(const uint32_t a[4][4], const uint32_t b[4][4],
                                         float acc[4][8][4]) {
#pragma unroll
    for (int mi = 0; mi < 4; ++mi)
#pragma unroll
        for (int ni = 0; ni < 8; ++ni) {
            uint32_t b0 = b[ni >> 1][(ni & 1) * 2];
            uint32_t b1 = b[ni >> 1][(ni & 1) * 2 + 1];
            MMA16816(acc[mi][ni][0], acc[mi][ni][1], acc[mi][ni][2], acc[mi][ni][3],
                     a[mi][0], a[mi][1], a[mi][2], a[mi][3], b0, b1);
        }
}

__global__ void __launch_bounds__(256, 1) gemm_kernel(const float* __restrict__ bias,
                                                      float* __restrict__ out) {
    extern __shared__ char smem[];
    const uint32_t sbase = smem_u32(smem);
    const int tid  = threadIdx.x;
    const int lane = tid & 31, wid = tid >> 5;
    const int wm = wid & 3, wn = wid >> 2;        // 4 x 2 warp grid
    const int arow_l = (lane & 7) + ((lane >> 3) & 1) * 8;
    const int a_c    = lane >> 4;
    const int brow_l = (lane & 7) + ((lane >> 4) & 1) * 8;
    const int b_c    = (lane >> 3) & 1;

    const uint32_t cta = blockIdx.x;
    const uint32_t start = (cta * TOTAL_CHUNKS) / NCTA;
    const uint32_t end   = ((cta + 1) * TOTAL_CHUNKS) / NCTA;

    float acc[4][8][4];
#pragma unroll
    for (int i = 0; i < 4; ++i)
#pragma unroll
        for (int j = 0; j < 8; ++j)
#pragma unroll
            for (int q = 0; q < 4; ++q) acc[i][j][q] = 0.f;

    uint32_t afrag[2][4][4], bfrag[2][4][4];
    uint32_t seg_first = start & 31u;             // first k-iter of current tile segment

    load_chunk(sbase + (start & 1u) * STAGE_BYTES, start, tid);
    asm volatile("cp.async.commit_group;" ::: "memory");

    for (uint32_t ch = start; ch < end; ++ch) {
        asm volatile("cp.async.wait_group 0;" ::: "memory");
        __syncthreads();

        const uint32_t sA = sbase + (ch & 1u) * STAGE_BYTES;
        const uint32_t sB = sA + A_BYTES;

        frag_load(sA, sB, 0, arow_l, a_c, brow_l, b_c, wm, wn, afrag[0], bfrag[0]);

        if (ch + 1 < end)
            load_chunk(sbase + ((ch + 1) & 1u) * STAGE_BYTES, ch + 1, tid);
        asm volatile("cp.async.commit_group;" ::: "memory");

#pragma unroll
        for (int s = 0; s < 8; ++s) {
            if (s < 7)
                frag_load(sA, sB, s + 1, arow_l, a_c, brow_l, b_c, wm, wn,
                          afrag[(s + 1) & 1], bfrag[(s + 1) & 1]);
            frag_mma(afrag[s & 1], bfrag[s & 1], acc);
        }

        const uint32_t kidx = ch & 31u;
        const bool tile_done = (kidx == 31u) || (ch + 1 == end);
        if (tile_done) {
            const uint32_t t = ch >> 5;
            const int n0 = (int)(t & 31u) * 128;
            const int m0 = (int)(t >> 5) * 256;
            const int ncol = n0 + wn * 64 + (lane & 3) * 2;
            const int mrow = m0 + wm * 64 + (lane >> 2);
            const bool full = (seg_first == 0u && kidx == 31u);
            if (full) {
#pragma unroll
                for (int mi = 0; mi < 4; ++mi) {
                    float* r0 = out + (size_t)(mrow + mi * 16) * OUT_F;
                    float* r1 = r0 + 8 * OUT_F;
#pragma unroll
                    for (int ni = 0; ni < 8; ++ni) {
                        float2 bv = *reinterpret_cast<const float2*>(bias + ncol + ni * 8);
                        float2 v0, v1;
                        v0.x = acc[mi][ni][0] + bv.x;
                        v0.y = acc[mi][ni][1] + bv.y;
                        v1.x = acc[mi][ni][2] + bv.x;
                        v1.y = acc[mi][ni][3] + bv.y;
                        *reinterpret_cast<float2*>(r0 + ncol + ni * 8) = v0;
                        *reinterpret_cast<float2*>(r1 + ncol + ni * 8) = v1;
                    }
                }
            } else {
#pragma unroll
                for (int mi = 0; mi < 4; ++mi) {
                    float* r0 = out + (size_t)(mrow + mi * 16) * OUT_F;
                    float* r1 = r0 + 8 * OUT_F;
#pragma unroll
                    for (int ni = 0; ni < 8; ++ni) {
                        redadd(r0 + ncol + ni * 8,     acc[mi][ni][0]);
                        redadd(r0 + ncol + ni * 8 + 1, acc[mi][ni][1]);
                        redadd(r1 + ncol + ni * 8,     acc[mi][ni][2]);
                        redadd(r1 + ncol + ni * 8 + 1, acc[mi][ni][3]);
                    }
                }
            }
#pragma unroll
            for (int i = 0; i < 4; ++i)
#pragma unroll
                for (int j = 0; j < 8; ++j)
#pragma unroll
                    for (int q = 0; q < 4; ++q) acc[i][j][q] = 0.f;
            seg_first = 0u;
        }
    }
}

// ---------------------------------------------------------- launch
extern "C" void kernel_launch(void* const* d_in, const int* in_sizes, int n_in,
                              void* d_out, int out_size) {
    const float* x    = (const float*)d_in[0];
    const int*   wq   = (const int*)d_in[1];
    const float* sw   = (const float*)d_in[2];
    const int*   perm = (const int*)d_in[3];   // int32 or int64 — detected on device
    const float* bias = (const float*)d_in[4];
    float* out = (float*)d_out;

    prep_kernel<<<4096 + MTOT + 147, 256>>>(wq, sw, x, perm, bias, out);

    cudaFuncSetAttribute(gemm_kernel, cudaFuncAttributeMaxDynamicSharedMemorySize, GEMM_SMEM);
    gemm_kernel<<<NCTA, 256, GEMM_SMEM>>>(bias, out);
}